// round 11
// baseline (speedup 1.0000x reference)
#include <cuda_runtime.h>
#include <cstdint>

#define LGRID  512
#define BATCH  32768
#define NCH    32
#define NCHUNK (LGRID / NCH)         // 16
#define TPB    256

typedef unsigned long long ull;

#define FMA2(d, a, b, c) asm("fma.rn.f32x2 %0, %1, %2, %3;" : "=l"(d) : "l"(a), "l"(b), "l"(c))
#define MUL2(d, a, b)    asm("mul.rn.f32x2 %0, %1, %2;"     : "=l"(d) : "l"(a), "l"(b))
#define ADD2(d, a, b)    asm("add.rn.f32x2 %0, %1, %2;"     : "=l"(d) : "l"(a), "l"(b))

__device__ __forceinline__ ull pack2(float lo, float hi) {
    ull r;
    asm("mov.b64 %0, {%1, %2};" : "=l"(r) : "f"(lo), "f"(hi));
    return r;
}
__device__ __forceinline__ ull pack2d(double v) {
    const float f = (float)v;
    return pack2(f, f);
}

struct V4 { float a, t, n, c; };

// ------------- single kernel: gvec prologue + closed-form coefficients + evaluation -------------
__global__ __launch_bounds__(TPB, 4)
void taylor_kernel(const float* __restrict__ s_grid,
                   const float* __restrict__ y0,
                   const float* __restrict__ w,
                   float* __restrict__ out) {
    __shared__ float sG[7][4][256];     // 28 KB Taylor vectors for this CTA's 256 trajectories
    __shared__ ull   sh_h[NCH];

    const int tid   = threadIdx.x;
    const int chunk = blockIdx.x >> 7;     // 128 CTAs per chunk
    const int cw    = blockIdx.x & 127;
    const int n0    = chunk * NCH;

    // packed (h,h) for this chunk's steps (exact fp32 grid diffs; last slot padded 0)
    if (tid < NCH) {
        const float h = (n0 + tid + 1 < LGRID)
                      ? (__ldg(s_grid + n0 + tid + 1) - __ldg(s_grid + n0 + tid))
                      : 0.0f;
        sh_h[tid] = pack2(h, h);
    }

    // ---- prologue: per-thread Taylor vectors for one trajectory ----
    {
        const int b = cw * 256 + tid;

        const float A = y0[0 * BATCH + b];
        const float T = y0[1 * BATCH + b];
        const float N = y0[2 * BATCH + b];
        const float C = y0[3 * BATCH + b];

        const float w0_  = __ldg(w + 0),  w1_  = __ldg(w + 1),  w2_  = __ldg(w + 2);
        const float w3_  = __ldg(w + 3),  w4_  = __ldg(w + 4),  w5_  = __ldg(w + 5);
        const float w6_  = __ldg(w + 6),  w7_  = __ldg(w + 7),  w8_  = __ldg(w + 8);
        const float w9_  = __ldg(w + 9),  w10_ = __ldg(w + 10), w11_ = __ldg(w + 11);
        const float w12_ = __ldg(w + 12), w13_ = __ldg(w + 13), w14_ = __ldg(w + 14);
        const float w15_ = __ldg(w + 15), w16_ = __ldg(w + 16), w17_ = __ldg(w + 17);
        const float w18_ = __ldg(w + 18), w19_ = __ldg(w + 19), w20_ = __ldg(w + 20);

        V4 f0;
        f0.a = fmaf(w2_, A * A, fmaf(w1_, A, w0_));
        f0.t = fmaf(w5_, T * T, fmaf(w4_, T, w3_)) + fmaf(w8_, A * T, fmaf(w7_, A * A, w6_ * A));
        f0.n = fmaf(w11_, N * N, fmaf(w10_, N, w9_)) + fmaf(w14_, T * N, fmaf(w13_, T * T, w12_ * T));
        f0.c = fmaf(w17_, C * C, fmaf(w16_, C, w15_)) + fmaf(w20_, N * C, fmaf(w19_, N * N, w18_ * N));

        const float jAA = fmaf(2.0f * w2_, A, w1_);
        const float jTA = fmaf(2.0f * w7_, A, fmaf(w8_, T, w6_));
        const float jTT = fmaf(2.0f * w5_, T, fmaf(w8_, A, w4_));
        const float jNT = fmaf(2.0f * w13_, T, fmaf(w14_, N, w12_));
        const float jNN = fmaf(2.0f * w11_, N, fmaf(w14_, T, w10_));
        const float jCN = fmaf(2.0f * w19_, N, fmaf(w20_, C, w18_));
        const float jCC = fmaf(2.0f * w17_, C, fmaf(w20_, N, w16_));

        auto applyJ = [&](const V4& v) {
            V4 r;
            r.a = jAA * v.a;
            r.t = fmaf(jTA, v.a, jTT * v.t);
            r.n = fmaf(jNT, v.t, jNN * v.n);
            r.c = fmaf(jCN, v.n, jCC * v.c);
            return r;
        };
        auto applyH = [&](const V4& u, const V4& v) {
            V4 r;
            r.a = 2.0f * w2_ * u.a * v.a;
            r.t = 2.0f * w5_ * u.t * v.t + 2.0f * w7_ * u.a * v.a + w8_ * (u.a * v.t + u.t * v.a);
            r.n = 2.0f * w11_ * u.n * v.n + 2.0f * w13_ * u.t * v.t + w14_ * (u.t * v.n + u.n * v.t);
            r.c = 2.0f * w17_ * u.c * v.c + 2.0f * w19_ * u.n * v.n + w20_ * (u.n * v.c + u.c * v.n);
            return r;
        };

        const V4 g2  = applyJ(f0);
        const V4 g3a = applyJ(g2);
        V4 h00 = applyH(f0, f0);
        h00.a *= 0.5f; h00.t *= 0.5f; h00.n *= 0.5f; h00.c *= 0.5f;
        const V4 g4a = applyJ(g3a);
        const V4 g4b = applyJ(h00);
        const V4 g4c = applyH(f0, g2);

        const V4 G[7] = { f0, g2, g3a, h00, g4a, g4b, g4c };
        #pragma unroll
        for (int m = 0; m < 7; ++m) {
            sG[m][0][tid] = G[m].a;
            sG[m][1][tid] = G[m].t;
            sG[m][2][tid] = G[m].n;
            sG[m][3][tid] = G[m].c;
        }
    }

    // ---- closed-form chunk-start coefficients (uniform-h, double precision) ----
    // exact prefix recurrence: S+=h; Q+=hS; R+=hS^2; P+=hQ; V+=hR; W+=hSQ; U+=hP
    // uniform-h closed forms (verified vs recurrence at small n):
    //   Q=h^2 n(n-1)/2, R=h^3 n(n-1)(2n-1)/6, P=h^3 n(n-1)(n-2)/6,
    //   U=h^4 n(n-1)(n-2)(n-3)/24, V=h^4 n(n-1)^2(n-2)/12, W=h^4 n(n-1)(n-2)(3n-1)/24
    ull S, Q, P, R, U, V, W;
    {
        const float s0f = __ldg(s_grid);
        const float snf = __ldg(s_grid + n0);
        const float slf = __ldg(s_grid + LGRID - 1);

        const double hb = ((double)slf - (double)s0f) / (double)(LGRID - 1);
        const double h2 = hb * hb;
        const double h3 = h2 * hb;
        const double h4 = h2 * h2;
        const double n  = (double)n0;
        const double n1 = n - 1.0, n2 = n - 2.0, n3 = n - 3.0;

        S = pack2(snf - s0f, snf - s0f);                       // exact from grid
        Q = pack2d(h2 * n * n1 * 0.5);
        R = pack2d(h3 * n * n1 * (2.0 * n - 1.0) / 6.0);
        P = pack2d(h3 * n * n1 * n2 / 6.0);
        U = pack2d(h4 * n * n1 * n2 * n3 / 24.0);
        V = pack2d(h4 * n * n1 * n1 * n2 / 12.0);
        W = pack2d(h4 * n * n1 * n2 * (3.0 * n - 1.0) / 24.0);
    }
    __syncthreads();

    // ---- gather component-split slices into registers ----
    const int lane = tid & 31;
    const int wid  = tid >> 5;
    const int c    = lane >> 3;
    const int q    = lane & 7;
    const int tw   = cw * 8 + wid;
    const int j0   = tw * 32 + q * 4;         // global trajectory base
    const int jl   = wid * 32 + q * 4;        // CTA-local trajectory base

    ull Glo[7], Ghi[7];
    #pragma unroll
    for (int m = 0; m < 7; ++m) {
        const float4 g4 = *(const float4*)&sG[m][c][jl];
        Glo[m] = pack2(g4.x, g4.y);
        Ghi[m] = pack2(g4.z, g4.w);
    }

    const float4 yv = *(const float4*)(y0 + (size_t)c * BATCH + j0);
    const ull ylo = pack2(yv.x, yv.y);
    const ull yhi = pack2(yv.z, yv.w);

    float* base = out + (size_t)n0 * (4 * BATCH) + (size_t)c * BATCH + j0;

    #pragma unroll 4
    for (int i = 0; i < NCH; ++i) {
        ull olo = ylo, ohi = yhi;
        FMA2(olo, S, Glo[0], olo);  FMA2(ohi, S, Ghi[0], ohi);
        FMA2(olo, Q, Glo[1], olo);  FMA2(ohi, Q, Ghi[1], ohi);
        FMA2(olo, P, Glo[2], olo);  FMA2(ohi, P, Ghi[2], ohi);
        FMA2(olo, R, Glo[3], olo);  FMA2(ohi, R, Ghi[3], ohi);
        FMA2(olo, U, Glo[4], olo);  FMA2(ohi, U, Ghi[4], ohi);
        FMA2(olo, V, Glo[5], olo);  FMA2(ohi, V, Ghi[5], ohi);
        FMA2(olo, W, Glo[6], olo);  FMA2(ohi, W, Ghi[6], ohi);

        asm volatile("st.global.cs.v2.u64 [%0], {%1, %2};"
                     :: "l"(base), "l"(olo), "l"(ohi) : "memory");

        // advance coefficients n -> n+1 with EXACT per-step h (reads pre-update values)
        const ull H = sh_h[i];
        ull t;
        MUL2(t, H, S);
        FMA2(U, H, P, U);
        FMA2(V, H, R, V);
        FMA2(P, H, Q, P);
        FMA2(W, t, Q, W);
        FMA2(R, t, S, R);
        ADD2(Q, Q, t);
        ADD2(S, S, H);

        base += 4 * BATCH;
    }
}

extern "C" void kernel_launch(void* const* d_in, const int* in_sizes, int n_in,
                              void* d_out, int out_size) {
    const float* s_grid = (const float*)d_in[0];
    const float* y0     = (const float*)d_in[1];
    const float* w      = (const float*)d_in[2];
    float* out          = (float*)d_out;

    taylor_kernel<<<NCHUNK * 128, TPB>>>(s_grid, y0, w, out);
}

// round 12
// speedup vs baseline: 3.5305x; 3.5305x over previous
#include <cuda_runtime.h>
#include <cstdint>

#define LGRID  512
#define BATCH  32768
#define NCH    32
#define NCHUNK (LGRID / NCH)         // 16
#define TPB    256

typedef unsigned long long ull;

#define FMA2(d, a, b, c) asm("fma.rn.f32x2 %0, %1, %2, %3;" : "=l"(d) : "l"(a), "l"(b), "l"(c))
#define MUL2(d, a, b)    asm("mul.rn.f32x2 %0, %1, %2;"     : "=l"(d) : "l"(a), "l"(b))
#define ADD2(d, a, b)    asm("add.rn.f32x2 %0, %1, %2;"     : "=l"(d) : "l"(a), "l"(b))

__device__ __forceinline__ ull pack2(float lo, float hi) {
    ull r;
    asm("mov.b64 %0, {%1, %2};" : "=l"(r) : "f"(lo), "f"(hi));
    return r;
}

struct V4 { float a, t, n, c; };

// single kernel: gvec prologue + fp32 closed-form coefficients + evaluation
__global__ __launch_bounds__(TPB, 4)
void taylor_kernel(const float* __restrict__ s_grid,
                   const float* __restrict__ y0,
                   const float* __restrict__ w,
                   float* __restrict__ out) {
    __shared__ float sG[7][4][256];     // 28 KB Taylor vectors for this CTA's 256 trajectories
    __shared__ ull   sh_h[NCH];

    const int tid   = threadIdx.x;
    const int chunk = blockIdx.x >> 7;     // 128 CTAs per chunk
    const int cw    = blockIdx.x & 127;
    const int n0    = chunk * NCH;

    // packed (h,h) for this chunk's steps (exact fp32 grid diffs; last slot padded 0)
    if (tid < NCH) {
        const float h = (n0 + tid + 1 < LGRID)
                      ? (__ldg(s_grid + n0 + tid + 1) - __ldg(s_grid + n0 + tid))
                      : 0.0f;
        sh_h[tid] = pack2(h, h);
    }

    // ---- prologue: per-thread Taylor vectors for one trajectory ----
    {
        const int b = cw * 256 + tid;

        const float A = y0[0 * BATCH + b];
        const float T = y0[1 * BATCH + b];
        const float N = y0[2 * BATCH + b];
        const float C = y0[3 * BATCH + b];

        const float w0_  = __ldg(w + 0),  w1_  = __ldg(w + 1),  w2_  = __ldg(w + 2);
        const float w3_  = __ldg(w + 3),  w4_  = __ldg(w + 4),  w5_  = __ldg(w + 5);
        const float w6_  = __ldg(w + 6),  w7_  = __ldg(w + 7),  w8_  = __ldg(w + 8);
        const float w9_  = __ldg(w + 9),  w10_ = __ldg(w + 10), w11_ = __ldg(w + 11);
        const float w12_ = __ldg(w + 12), w13_ = __ldg(w + 13), w14_ = __ldg(w + 14);
        const float w15_ = __ldg(w + 15), w16_ = __ldg(w + 16), w17_ = __ldg(w + 17);
        const float w18_ = __ldg(w + 18), w19_ = __ldg(w + 19), w20_ = __ldg(w + 20);

        V4 f0;
        f0.a = fmaf(w2_, A * A, fmaf(w1_, A, w0_));
        f0.t = fmaf(w5_, T * T, fmaf(w4_, T, w3_)) + fmaf(w8_, A * T, fmaf(w7_, A * A, w6_ * A));
        f0.n = fmaf(w11_, N * N, fmaf(w10_, N, w9_)) + fmaf(w14_, T * N, fmaf(w13_, T * T, w12_ * T));
        f0.c = fmaf(w17_, C * C, fmaf(w16_, C, w15_)) + fmaf(w20_, N * C, fmaf(w19_, N * N, w18_ * N));

        const float jAA = fmaf(2.0f * w2_, A, w1_);
        const float jTA = fmaf(2.0f * w7_, A, fmaf(w8_, T, w6_));
        const float jTT = fmaf(2.0f * w5_, T, fmaf(w8_, A, w4_));
        const float jNT = fmaf(2.0f * w13_, T, fmaf(w14_, N, w12_));
        const float jNN = fmaf(2.0f * w11_, N, fmaf(w14_, T, w10_));
        const float jCN = fmaf(2.0f * w19_, N, fmaf(w20_, C, w18_));
        const float jCC = fmaf(2.0f * w17_, C, fmaf(w20_, N, w16_));

        auto applyJ = [&](const V4& v) {
            V4 r;
            r.a = jAA * v.a;
            r.t = fmaf(jTA, v.a, jTT * v.t);
            r.n = fmaf(jNT, v.t, jNN * v.n);
            r.c = fmaf(jCN, v.n, jCC * v.c);
            return r;
        };
        auto applyH = [&](const V4& u, const V4& v) {
            V4 r;
            r.a = 2.0f * w2_ * u.a * v.a;
            r.t = 2.0f * w5_ * u.t * v.t + 2.0f * w7_ * u.a * v.a + w8_ * (u.a * v.t + u.t * v.a);
            r.n = 2.0f * w11_ * u.n * v.n + 2.0f * w13_ * u.t * v.t + w14_ * (u.t * v.n + u.n * v.t);
            r.c = 2.0f * w17_ * u.c * v.c + 2.0f * w19_ * u.n * v.n + w20_ * (u.n * v.c + u.c * v.n);
            return r;
        };

        const V4 g2  = applyJ(f0);
        const V4 g3a = applyJ(g2);
        V4 h00 = applyH(f0, f0);
        h00.a *= 0.5f; h00.t *= 0.5f; h00.n *= 0.5f; h00.c *= 0.5f;
        const V4 g4a = applyJ(g3a);
        const V4 g4b = applyJ(h00);
        const V4 g4c = applyH(f0, g2);

        const V4 G[7] = { f0, g2, g3a, h00, g4a, g4b, g4c };
        #pragma unroll
        for (int m = 0; m < 7; ++m) {
            sG[m][0][tid] = G[m].a;
            sG[m][1][tid] = G[m].t;
            sG[m][2][tid] = G[m].n;
            sG[m][3][tid] = G[m].c;
        }
    }

    // ---- closed-form chunk-start coefficients (uniform-h, fp32, no divisions) ----
    // prefix recurrence: S+=h; Q+=hS; R+=hS^2; P+=hQ; V+=hR; W+=hSQ; U+=hP
    // uniform-h closed forms:
    //   Q=h^2 n(n-1)/2, R=h^3 n(n-1)(2n-1)/6, P=h^3 n(n-1)(n-2)/6,
    //   U=h^4 n(n-1)(n-2)(n-3)/24, V=h^4 n(n-1)^2(n-2)/12, W=h^4 n(n-1)(n-2)(3n-1)/24
    ull S, Q, P, R, U, V, W;
    {
        const float s0f = __ldg(s_grid);
        const float snf = __ldg(s_grid + n0);
        const float slf = __ldg(s_grid + LGRID - 1);

        const float hb = (slf - s0f) * (1.0f / (float)(LGRID - 1));
        const float h2 = hb * hb;
        const float h3 = h2 * hb;
        const float h4 = h2 * h2;
        const float n  = (float)n0;
        const float n1 = n - 1.0f, n2 = n - 2.0f, n3 = n - 3.0f;

        const float nn1 = n * n1;

        const float Sf = snf - s0f;                                   // exact from grid
        const float Qf = h2 * nn1 * 0.5f;
        const float Rf = h3 * nn1 * (2.0f * n - 1.0f) * (1.0f / 6.0f);
        const float Pf = h3 * nn1 * n2 * (1.0f / 6.0f);
        const float Uf = h4 * nn1 * n2 * n3 * (1.0f / 24.0f);
        const float Vf = h4 * nn1 * n1 * n2 * (1.0f / 12.0f);
        const float Wf = h4 * nn1 * n2 * (3.0f * n - 1.0f) * (1.0f / 24.0f);

        S = pack2(Sf, Sf);
        Q = pack2(Qf, Qf);
        R = pack2(Rf, Rf);
        P = pack2(Pf, Pf);
        U = pack2(Uf, Uf);
        V = pack2(Vf, Vf);
        W = pack2(Wf, Wf);
    }
    __syncthreads();

    // ---- gather component-split slices into registers ----
    const int lane = tid & 31;
    const int wid  = tid >> 5;
    const int c    = lane >> 3;
    const int q    = lane & 7;
    const int tw   = cw * 8 + wid;
    const int j0   = tw * 32 + q * 4;         // global trajectory base
    const int jl   = wid * 32 + q * 4;        // CTA-local trajectory base

    ull Glo[7], Ghi[7];
    #pragma unroll
    for (int m = 0; m < 7; ++m) {
        const float4 g4 = *(const float4*)&sG[m][c][jl];
        Glo[m] = pack2(g4.x, g4.y);
        Ghi[m] = pack2(g4.z, g4.w);
    }

    const float4 yv = *(const float4*)(y0 + (size_t)c * BATCH + j0);
    const ull ylo = pack2(yv.x, yv.y);
    const ull yhi = pack2(yv.z, yv.w);

    float* base = out + (size_t)n0 * (4 * BATCH) + (size_t)c * BATCH + j0;

    #pragma unroll 4
    for (int i = 0; i < NCH; ++i) {
        ull olo = ylo, ohi = yhi;
        FMA2(olo, S, Glo[0], olo);  FMA2(ohi, S, Ghi[0], ohi);
        FMA2(olo, Q, Glo[1], olo);  FMA2(ohi, Q, Ghi[1], ohi);
        FMA2(olo, P, Glo[2], olo);  FMA2(ohi, P, Ghi[2], ohi);
        FMA2(olo, R, Glo[3], olo);  FMA2(ohi, R, Ghi[3], ohi);
        FMA2(olo, U, Glo[4], olo);  FMA2(ohi, U, Ghi[4], ohi);
        FMA2(olo, V, Glo[5], olo);  FMA2(ohi, V, Ghi[5], ohi);
        FMA2(olo, W, Glo[6], olo);  FMA2(ohi, W, Ghi[6], ohi);

        asm volatile("st.global.cs.v2.u64 [%0], {%1, %2};"
                     :: "l"(base), "l"(olo), "l"(ohi) : "memory");

        // advance coefficients n -> n+1 with EXACT per-step h (reads pre-update values)
        const ull H = sh_h[i];
        ull t;
        MUL2(t, H, S);
        FMA2(U, H, P, U);
        FMA2(V, H, R, V);
        FMA2(P, H, Q, P);
        FMA2(W, t, Q, W);
        FMA2(R, t, S, R);
        ADD2(Q, Q, t);
        ADD2(S, S, H);

        base += 4 * BATCH;
    }
}

extern "C" void kernel_launch(void* const* d_in, const int* in_sizes, int n_in,
                              void* d_out, int out_size) {
    const float* s_grid = (const float*)d_in[0];
    const float* y0     = (const float*)d_in[1];
    const float* w      = (const float*)d_in[2];
    float* out          = (float*)d_out;

    taylor_kernel<<<NCHUNK * 128, TPB>>>(s_grid, y0, w, out);
}